// round 6
// baseline (speedup 1.0000x reference)
#include <cuda_runtime.h>
#include <cstdint>

#define BATCH 16
#define NPTS  8192
#define NGRP  512
#define GSZ   32

// ---------------------------------------------------------------------------
// Stage 1: Farthest-point sampling. One CTA per batch; xyz and min_d live in
// registers (8 points/thread @ 1024 threads). Per iteration: distance update,
// fused running argmax (strict >, ascending index scan == first-max), warp
// shuffle reduction with (value, min-index) tie-break, block reduction, and
// broadcast of the newly picked point's coordinates from its owner thread.
// Centers are written directly into the output buffer's centers region.
// ---------------------------------------------------------------------------
#define FPS_TPB 1024
#define FPS_PPT (NPTS / FPS_TPB)   // 8

__global__ __launch_bounds__(FPS_TPB, 1)
void fps_kernel(const float* __restrict__ points, float* __restrict__ centers)
{
    const int b = blockIdx.x;
    const int t = threadIdx.x;
    const float* pb = points + (size_t)b * NPTS * 6;

    float x[FPS_PPT], y[FPS_PPT], z[FPS_PPT], md[FPS_PPT];
#pragma unroll
    for (int i = 0; i < FPS_PPT; i++) {
        int p = i * FPS_TPB + t;
        x[i] = pb[p * 6 + 0];
        y[i] = pb[p * 6 + 1];
        z[i] = pb[p * 6 + 2];
        md[i] = __int_as_float(0x7f800000);  // +inf
    }

    __shared__ float s_last[3];
    __shared__ float s_wv[32];
    __shared__ int   s_wi[32];
    __shared__ int   s_nxt;
    if (t == 0) { s_last[0] = pb[0]; s_last[1] = pb[1]; s_last[2] = pb[2]; }
    __syncthreads();

    const int lane = t & 31;
    const int wid  = t >> 5;
    float* cb = centers + (size_t)b * NGRP * 3;

    for (int g = 0; g < NGRP; g++) {
        const float lx = s_last[0], ly = s_last[1], lz = s_last[2];
        if (t == 0) { cb[g * 3 + 0] = lx; cb[g * 3 + 1] = ly; cb[g * 3 + 2] = lz; }

        float bv = -1.0f;
        int   bi = 0;
#pragma unroll
        for (int i = 0; i < FPS_PPT; i++) {
            float dx = x[i] - lx;
            float dy = y[i] - ly;
            float dz = z[i] - lz;
            float d  = fmaf(dz, dz, fmaf(dy, dy, dx * dx));
            float m  = fminf(md[i], d);
            md[i] = m;
            if (m > bv) { bv = m; bi = i * FPS_TPB + t; }   // strict >: keeps lowest idx
        }
        // warp max-reduce with lowest-index tie-break (matches jnp.argmax)
#pragma unroll
        for (int o = 16; o > 0; o >>= 1) {
            float ov = __shfl_down_sync(0xffffffffu, bv, o);
            int   oi = __shfl_down_sync(0xffffffffu, bi, o);
            if (ov > bv || (ov == bv && oi < bi)) { bv = ov; bi = oi; }
        }
        if (lane == 0) { s_wv[wid] = bv; s_wi[wid] = bi; }
        __syncthreads();
        if (wid == 0) {
            bv = s_wv[lane];
            bi = s_wi[lane];
#pragma unroll
            for (int o = 16; o > 0; o >>= 1) {
                float ov = __shfl_down_sync(0xffffffffu, bv, o);
                int   oi = __shfl_down_sync(0xffffffffu, bi, o);
                if (ov > bv || (ov == bv && oi < bi)) { bv = ov; bi = oi; }
            }
            if (lane == 0) s_nxt = bi;
        }
        __syncthreads();
        const int nxt = s_nxt;
        if ((nxt & (FPS_TPB - 1)) == t) {       // owner broadcasts new point
            int i = nxt >> 10;                   // log2(FPS_TPB)
            s_last[0] = x[i]; s_last[1] = y[i]; s_last[2] = z[i];
        }
        __syncthreads();
    }
}

// ---------------------------------------------------------------------------
// Stage 2: KNN (top-32 smallest d2, sorted ascending, ties -> lower index,
// matching lax.top_k on -d2) + gather + center-relative xyz.
// One warp per group (2 groups/warp). The running top-32 list is held sorted
// across the 32 lanes. Per 32 candidates: ballot against the current 32nd
// distance; if any candidate qualifies, bitonic-sort candidates and do a
// bitonic 32+32 -> 32 merge. xyz + |x|^2 staged in shared as float4 (LDS.128).
// d2 uses the reference formula cc - 2*dot + |x|^2.
// ---------------------------------------------------------------------------
#define KNN_TPB        1024
#define KNN_CTAS_PER_B 8
#define GRP_PER_CTA    (NGRP / KNN_CTAS_PER_B)        // 64
#define WARPS_PER_CTA  (KNN_TPB / 32)                 // 32
#define GRP_PER_WARP   (GRP_PER_CTA / WARPS_PER_CTA)  // 2

__device__ __forceinline__ bool lessp(float v1, int i1, float v2, int i2)
{
    return (v1 < v2) || (v1 == v2 && i1 < i2);
}

__global__ __launch_bounds__(KNN_TPB, 1)
void knn_kernel(const float* __restrict__ points,
                const float* __restrict__ centers,
                float* __restrict__ grouped)
{
    extern __shared__ float4 s4[];
    const int b    = blockIdx.y;
    const int cta  = blockIdx.x;
    const int t    = threadIdx.x;
    const int lane = t & 31;
    const int wid  = t >> 5;
    const float* pb = points + (size_t)b * NPTS * 6;

    // stage xyz + |x|^2 in shared
    for (int p = t; p < NPTS; p += KNN_TPB) {
        float px = pb[p * 6 + 0];
        float py = pb[p * 6 + 1];
        float pz = pb[p * 6 + 2];
        float xx = fmaf(pz, pz, fmaf(py, py, px * px));
        s4[p] = make_float4(px, py, pz, xx);
    }
    __syncthreads();

#pragma unroll
    for (int r = 0; r < GRP_PER_WARP; r++) {
        const int g = cta * GRP_PER_CTA + r * WARPS_PER_CTA + wid;
        const float* c = centers + ((size_t)b * NGRP + g) * 3;
        const float cx = c[0], cy = c[1], cz = c[2];
        const float cc = fmaf(cz, cz, fmaf(cy, cy, cx * cx));
        const float m2x = -2.0f * cx, m2y = -2.0f * cy, m2z = -2.0f * cz;

        float Lv = __int_as_float(0x7f800000);   // +inf
        int   Li = 0x7fffffff;

        for (int nb = 0; nb < NPTS / 32; nb++) {
            const int p = nb * 32 + lane;
            float4 q = s4[p];
            float tt = fmaf(q.x, m2x, cc);
            tt = fmaf(q.y, m2y, tt);
            tt = fmaf(q.z, m2z, tt);
            const float d = tt + q.w;

            const float tv = __shfl_sync(0xffffffffu, Lv, 31);
            const int   ti = __shfl_sync(0xffffffffu, Li, 31);
            const bool ins = lessp(d, p, tv, ti);
            if (__any_sync(0xffffffffu, ins)) {
                float cv = d;
                int   ci = p;
                // bitonic sort 32 candidates ascending (strict total order via idx)
#pragma unroll
                for (int k = 2; k <= 32; k <<= 1) {
#pragma unroll
                    for (int j = k >> 1; j >= 1; j >>= 1) {
                        float ov = __shfl_xor_sync(0xffffffffu, cv, j);
                        int   oi = __shfl_xor_sync(0xffffffffu, ci, j);
                        bool asc = ((lane & k) == 0);
                        bool lo  = ((lane & j) == 0);
                        bool take = (asc == lo) ? lessp(ov, oi, cv, ci)
                                                : lessp(cv, ci, ov, oi);
                        if (take) { cv = ov; ci = oi; }
                    }
                }
                // merge: pair L[lane] with reversed C -> 32 smallest (bitonic)
                float mv = __shfl_sync(0xffffffffu, cv, 31 - lane);
                int   mi = __shfl_sync(0xffffffffu, ci, 31 - lane);
                if (lessp(mv, mi, Lv, Li)) { Lv = mv; Li = mi; }
                // bitonic merge network, ascending
#pragma unroll
                for (int j = 16; j >= 1; j >>= 1) {
                    float ov = __shfl_xor_sync(0xffffffffu, Lv, j);
                    int   oi = __shfl_xor_sync(0xffffffffu, Li, j);
                    bool lo = ((lane & j) == 0);
                    bool take = lo ? lessp(ov, oi, Lv, Li)
                                   : lessp(Lv, Li, ov, oi);
                    if (take) { Lv = ov; Li = oi; }
                }
            }
        }

        // gather: lane k holds k-th nearest neighbor (ascending distance)
        const float* pp = pb + (size_t)Li * 6;
        float o0 = pp[0] - cx;
        float o1 = pp[1] - cy;
        float o2 = pp[2] - cz;
        float o3 = pp[3];
        float o4 = pp[4];
        float o5 = pp[5];
        float* o = grouped + ((((size_t)b * NGRP + g) * GSZ) + lane) * 6;
        o[0] = o0; o[1] = o1; o[2] = o2; o[3] = o3; o[4] = o4; o[5] = o5;
    }
}

// ---------------------------------------------------------------------------
// Launch: fps writes centers into the tail of d_out; knn consumes them
// (same stream => ordered). Output layout: grouped [16,512,32,6] then
// centers [16,512,3], both float32.
// ---------------------------------------------------------------------------
extern "C" void kernel_launch(void* const* d_in, const int* in_sizes, int n_in,
                              void* d_out, int out_size)
{
    const float* points = (const float*)d_in[0];
    float* out     = (float*)d_out;
    float* grouped = out;
    float* centers = out + (size_t)BATCH * NGRP * GSZ * 6;

    cudaFuncSetAttribute(knn_kernel, cudaFuncAttributeMaxDynamicSharedMemorySize,
                         NPTS * (int)sizeof(float4));

    fps_kernel<<<BATCH, FPS_TPB>>>(points, centers);
    knn_kernel<<<dim3(KNN_CTAS_PER_B, BATCH), KNN_TPB, NPTS * sizeof(float4)>>>(
        points, centers, grouped);
}

// round 10
// speedup vs baseline: 2.5015x; 2.5015x over previous
#include <cuda_runtime.h>
#include <cstdint>

#define BATCH 16
#define NPTS  8192
#define NGRP  512
#define GSZ   32

typedef unsigned long long ull;

// ---- packed f32x2 helpers (Blackwell packed fp32 pipe) ----------------------
__device__ __forceinline__ ull f2_add(ull a, ull b) {
    ull r; asm("add.rn.f32x2 %0, %1, %2;" : "=l"(r) : "l"(a), "l"(b)); return r;
}
__device__ __forceinline__ ull f2_mul(ull a, ull b) {
    ull r; asm("mul.rn.f32x2 %0, %1, %2;" : "=l"(r) : "l"(a), "l"(b)); return r;
}
__device__ __forceinline__ ull f2_fma(ull a, ull b, ull c) {
    ull r; asm("fma.rn.f32x2 %0, %1, %2, %3;" : "=l"(r) : "l"(a), "l"(b), "l"(c)); return r;
}
__device__ __forceinline__ ull f2_pack(float lo, float hi) {
    ull r; asm("mov.b64 %0, {%1, %2};" : "=l"(r) : "f"(lo), "f"(hi)); return r;
}
__device__ __forceinline__ float2 f2_unpack(ull v) {
    float lo, hi; asm("mov.b64 {%0, %1}, %2;" : "=f"(lo), "=f"(hi) : "l"(v));
    return make_float2(lo, hi);
}

// ---------------------------------------------------------------------------
// Stage 1: FPS. One CTA/batch, 1024 threads, 8 pts/thread in registers
// (packed f32x2 pairs). Per iteration:
//   - packed distance update + fminf + running argmax (strict >, ascending
//     scan == first-max, matching jnp.argmax)
//   - warp reduce via redux.max on float bits (d2 >= 0 -> monotone) +
//     equality ballot + redux.min on index (lowest-index tie-break)
//   - block reduce in warp 0 the same way; lane 0 fetches winner coords from
//     an smem mirror of xyz and writes s_last + the center. 2 barriers/iter.
// ---------------------------------------------------------------------------
#define FPS_TPB 1024

__global__ __launch_bounds__(FPS_TPB, 1)
void fps_kernel(const float* __restrict__ points, float* __restrict__ centers)
{
    extern __shared__ float fsm[];
    float*    s_x    = fsm;                 // [NPTS]
    float*    s_y    = fsm + NPTS;          // [NPTS]
    float*    s_z    = fsm + 2 * NPTS;      // [NPTS]
    float*    s_last = fsm + 3 * NPTS;      // [4]
    unsigned* s_wv   = (unsigned*)(s_last + 4);   // [32]
    int*      s_wi   = (int*)(s_wv + 32);         // [32]

    const int b = blockIdx.x;
    const int t = threadIdx.x;
    const int lane = t & 31;
    const int wid  = t >> 5;
    const float* pb = points + (size_t)b * NPTS * 6;

    ull px[4], py[4], pz[4];
    float md[8];
#pragma unroll
    for (int j = 0; j < 4; j++) {
        int p0 = (2 * j) * FPS_TPB + t;
        int p1 = (2 * j + 1) * FPS_TPB + t;
        float x0 = pb[p0 * 6 + 0], y0 = pb[p0 * 6 + 1], z0 = pb[p0 * 6 + 2];
        float x1 = pb[p1 * 6 + 0], y1 = pb[p1 * 6 + 1], z1 = pb[p1 * 6 + 2];
        px[j] = f2_pack(x0, x1); py[j] = f2_pack(y0, y1); pz[j] = f2_pack(z0, z1);
        s_x[p0] = x0; s_y[p0] = y0; s_z[p0] = z0;
        s_x[p1] = x1; s_y[p1] = y1; s_z[p1] = z1;
        md[2 * j] = __int_as_float(0x7f800000);
        md[2 * j + 1] = __int_as_float(0x7f800000);
    }
    if (t == 0) { s_last[0] = pb[0]; s_last[1] = pb[1]; s_last[2] = pb[2]; }
    __syncthreads();

    float* cb = centers + (size_t)b * NGRP * 3;

    for (int g = 0; g < NGRP; g++) {
        const float lx = s_last[0], ly = s_last[1], lz = s_last[2];
        const ull nlx = f2_pack(-lx, -lx);
        const ull nly = f2_pack(-ly, -ly);
        const ull nlz = f2_pack(-lz, -lz);

        float bv = -1.0f;
        int   bi = 0;
#pragma unroll
        for (int j = 0; j < 4; j++) {
            ull dx = f2_add(px[j], nlx);
            ull dy = f2_add(py[j], nly);
            ull dz = f2_add(pz[j], nlz);
            ull dd = f2_mul(dx, dx);
            dd = f2_fma(dy, dy, dd);
            dd = f2_fma(dz, dz, dd);
            float2 d = f2_unpack(dd);
            float m0 = fminf(md[2 * j], d.x);     md[2 * j] = m0;
            if (m0 > bv) { bv = m0; bi = (2 * j) * FPS_TPB + t; }
            float m1 = fminf(md[2 * j + 1], d.y); md[2 * j + 1] = m1;
            if (m1 > bv) { bv = m1; bi = (2 * j + 1) * FPS_TPB + t; }
        }
        // warp reduce: max on value bits (>=0), then min index among equals
        unsigned u  = __float_as_uint(bv);
        unsigned wm = __reduce_max_sync(0xffffffffu, u);
        unsigned ci = (u == wm) ? (unsigned)bi : 0xffffffffu;
        unsigned wi = __reduce_min_sync(0xffffffffu, ci);
        if (lane == 0) { s_wv[wid] = wm; s_wi[wid] = (int)wi; }
        __syncthreads();
        if (wid == 0) {
            unsigned u2 = s_wv[lane];
            unsigned i2 = (unsigned)s_wi[lane];
            unsigned m2 = __reduce_max_sync(0xffffffffu, u2);
            unsigned c2 = (u2 == m2) ? i2 : 0xffffffffu;
            unsigned nxt = __reduce_min_sync(0xffffffffu, c2);
            if (lane == 0) {
                cb[g * 3 + 0] = lx; cb[g * 3 + 1] = ly; cb[g * 3 + 2] = lz;
                s_last[0] = s_x[nxt]; s_last[1] = s_y[nxt]; s_last[2] = s_z[nxt];
            }
        }
        __syncthreads();
    }
}

// ---------------------------------------------------------------------------
// Stage 2: KNN top-32 (ascending d2, lower-index tie -> matches lax.top_k on
// -d2) + gather + center-relative xyz. One warp per group; sorted top-32 held
// across the 32 lanes. Batch 0 bulk-fills via one bitonic sort; thereafter
// each qualifying candidate is inserted via rank = popc(ballot) + shfl_up
// shift (~210 expected insertions/group). Threshold (d,idx of lane 31) is
// kept broadcast in registers. xyz + |x|^2 staged in smem as float4.
// ---------------------------------------------------------------------------
#define KNN_TPB        1024
#define KNN_CTAS_PER_B 8
#define GRP_PER_CTA    (NGRP / KNN_CTAS_PER_B)        // 64
#define WARPS_PER_CTA  (KNN_TPB / 32)                 // 32
#define GRP_PER_WARP   (GRP_PER_CTA / WARPS_PER_CTA)  // 2

__device__ __forceinline__ bool lessp(float v1, int i1, float v2, int i2)
{
    return (v1 < v2) || (v1 == v2 && i1 < i2);
}

__global__ __launch_bounds__(KNN_TPB, 1)
void knn_kernel(const float* __restrict__ points,
                const float* __restrict__ centers,
                float* __restrict__ grouped)
{
    extern __shared__ float4 s4[];
    const int b    = blockIdx.y;
    const int cta  = blockIdx.x;
    const int t    = threadIdx.x;
    const int lane = t & 31;
    const int wid  = t >> 5;
    const float* pb = points + (size_t)b * NPTS * 6;

    for (int p = t; p < NPTS; p += KNN_TPB) {
        float pxv = pb[p * 6 + 0];
        float pyv = pb[p * 6 + 1];
        float pzv = pb[p * 6 + 2];
        float xx = fmaf(pzv, pzv, fmaf(pyv, pyv, pxv * pxv));
        s4[p] = make_float4(pxv, pyv, pzv, xx);
    }
    __syncthreads();

    const unsigned FULL = 0xffffffffu;

#pragma unroll
    for (int r = 0; r < GRP_PER_WARP; r++) {
        const int g = cta * GRP_PER_CTA + r * WARPS_PER_CTA + wid;
        const float* c = centers + ((size_t)b * NGRP + g) * 3;
        const float cx = c[0], cy = c[1], cz = c[2];
        const float cc = fmaf(cz, cz, fmaf(cy, cy, cx * cx));
        const float m2x = -2.0f * cx, m2y = -2.0f * cy, m2z = -2.0f * cz;

        float Lv; int Li;
        // ---- batch 0: bitonic sort the first 32 candidates -> initial list
        {
            float4 q = s4[lane];
            float tt = fmaf(q.x, m2x, cc);
            tt = fmaf(q.y, m2y, tt);
            tt = fmaf(q.z, m2z, tt);
            float cv = tt + q.w;
            int   ci = lane;
#pragma unroll
            for (int k = 2; k <= 32; k <<= 1) {
#pragma unroll
                for (int j = k >> 1; j >= 1; j >>= 1) {
                    float ov = __shfl_xor_sync(FULL, cv, j);
                    int   oi = __shfl_xor_sync(FULL, ci, j);
                    bool asc = ((lane & k) == 0);
                    bool lo  = ((lane & j) == 0);
                    bool take = (asc == lo) ? lessp(ov, oi, cv, ci)
                                            : lessp(cv, ci, ov, oi);
                    if (take) { cv = ov; ci = oi; }
                }
            }
            Lv = cv; Li = ci;
        }
        float tv = __shfl_sync(FULL, Lv, 31);
        int   ti = __shfl_sync(FULL, Li, 31);

        for (int nb = 1; nb < NPTS / 32; nb++) {
            const int p = nb * 32 + lane;
            float4 q = s4[p];
            float tt = fmaf(q.x, m2x, cc);
            tt = fmaf(q.y, m2y, tt);
            tt = fmaf(q.z, m2z, tt);
            const float d = tt + q.w;

            unsigned pend = __ballot_sync(FULL, lessp(d, p, tv, ti));
            while (pend) {
                const int src = __ffs(pend) - 1;
                pend &= pend - 1;
                const float cd = __shfl_sync(FULL, d, src);
                const int   cp = __shfl_sync(FULL, p, src);
                if (lessp(cd, cp, tv, ti)) {   // uniform re-check (threshold moved)
                    unsigned mk = __ballot_sync(FULL, lessp(Lv, Li, cd, cp));
                    int rank = __popc(mk);     // prefix mask -> insert position
                    float pv = __shfl_up_sync(FULL, Lv, 1);
                    int   pi = __shfl_up_sync(FULL, Li, 1);
                    if (lane == rank)      { Lv = cd; Li = cp; }
                    else if (lane > rank)  { Lv = pv; Li = pi; }
                    tv = __shfl_sync(FULL, Lv, 31);
                    ti = __shfl_sync(FULL, Li, 31);
                }
            }
        }

        // gather: lane k holds k-th nearest neighbor (ascending)
        const float* pp = pb + (size_t)Li * 6;
        float o0 = pp[0] - cx;
        float o1 = pp[1] - cy;
        float o2 = pp[2] - cz;
        float o3 = pp[3];
        float o4 = pp[4];
        float o5 = pp[5];
        float* o = grouped + ((((size_t)b * NGRP + g) * GSZ) + lane) * 6;
        o[0] = o0; o[1] = o1; o[2] = o2; o[3] = o3; o[4] = o4; o[5] = o5;
    }
}

// ---------------------------------------------------------------------------
// Output layout: grouped [16,512,32,6] then centers [16,512,3], float32.
// fps writes centers into the tail of d_out; knn consumes them (same stream).
// ---------------------------------------------------------------------------
extern "C" void kernel_launch(void* const* d_in, const int* in_sizes, int n_in,
                              void* d_out, int out_size)
{
    const float* points = (const float*)d_in[0];
    float* out     = (float*)d_out;
    float* grouped = out;
    float* centers = out + (size_t)BATCH * NGRP * GSZ * 6;

    const int fps_smem = (3 * NPTS + 4) * (int)sizeof(float)
                       + 32 * (int)sizeof(unsigned) + 32 * (int)sizeof(int);
    const int knn_smem = NPTS * (int)sizeof(float4);

    cudaFuncSetAttribute(fps_kernel, cudaFuncAttributeMaxDynamicSharedMemorySize,
                         fps_smem);
    cudaFuncSetAttribute(knn_kernel, cudaFuncAttributeMaxDynamicSharedMemorySize,
                         knn_smem);

    fps_kernel<<<BATCH, FPS_TPB, fps_smem>>>(points, centers);
    knn_kernel<<<dim3(KNN_CTAS_PER_B, BATCH), KNN_TPB, knn_smem>>>(
        points, centers, grouped);
}